// round 1
// baseline (speedup 1.0000x reference)
#include <cuda_runtime.h>
#include <cuda_fp16.h>

#define W_IMG 1216
#define H_IMG 352
#define NB    4
#define HW    (H_IMG * W_IMG)     /* 428032 */
#define CHG   27                  /* guidance channels */
#define PT    3                   /* prop steps */

/* conv tile */
#define TW    128
#define TH    2
#define GSW   132                 /* 130 used cols, padded */
#define WPAD  28                  /* 27 oc padded to 28 for 16B rows */

#define SMEM_BYTES ((CHG * 4 * GSW + 243 * WPAD) * 4)

/* ---------- packed f32x2 helpers (Blackwell FFMA2) ---------- */
__device__ __forceinline__ unsigned long long pack2f(float a, float b) {
    unsigned long long r;
    asm("mov.b64 %0, {%1, %2};" : "=l"(r)
        : "r"(__float_as_uint(a)), "r"(__float_as_uint(b)));
    return r;
}
__device__ __forceinline__ unsigned long long ffma2(unsigned long long a,
                                                    unsigned long long b,
                                                    unsigned long long c) {
    unsigned long long d;
    asm("fma.rn.f32x2 %0, %1, %2, %3;" : "=l"(d) : "l"(a), "l"(b), "l"(c));
    return d;
}
__device__ __forceinline__ void unpack2f(unsigned long long v, float& lo, float& hi) {
    unsigned int a, b;
    asm("mov.b64 {%0, %1}, %2;" : "=r"(a), "=r"(b) : "l"(v));
    lo = __uint_as_float(a);
    hi = __uint_as_float(b);
}

/* ---------------------------------------------------------------
 * Conv 3x3 (27 -> 81 ch, SAME, zero pad), fused with:
 *   - fp16 round of the 18 offset channels per prop step
 *   - softmax over the 9 affinity channels per prop step + fp16 round
 * writes straight into the d_out offsets/affs regions (f32 values).
 * --------------------------------------------------------------- */
__global__ void __launch_bounds__(256, 2)
conv_off_aff_kernel(const float* __restrict__ g,
                    const float* __restrict__ w_off,
                    const float* __restrict__ b_off,
                    float* __restrict__ out_off,
                    float* __restrict__ out_aff)
{
    extern __shared__ float sm[];
    float* gs  = sm;                        /* CHG*4*GSW guidance patch   */
    float* wsm = sm + CHG * 4 * GSW;        /* 243*WPAD weights (1 group) */

    const int tid = threadIdx.x;
    const int tx  = tid & (TW - 1);
    const int ty  = tid >> 7;
    const int w0  = blockIdx.x * TW;
    const int h0  = blockIdx.y * TH;
    const int b   = blockIdx.z;

    /* cooperative guidance patch load: rows h0-1 .. h0+2, cols w0-1 .. w0+128 */
    const int GTOT = CHG * 4 * 130;
    for (int i = tid; i < GTOT; i += 256) {
        int c  = i % 130;
        int t2 = i / 130;
        int r  = t2 & 3;
        int ic = t2 >> 2;
        int gh = h0 - 1 + r;
        int gw = w0 - 1 + c;
        float v = 0.f;
        if ((unsigned)gh < H_IMG && (unsigned)gw < W_IMG)
            v = g[(size_t)(b * CHG + ic) * HW + gh * W_IMG + gw];
        gs[(ic * 4 + r) * GSW + c] = v;
    }

    const int  wc    = w0 + tx;
    const int  h     = h0 + ty;
    const bool valid = (wc < W_IMG);
    const int  pix   = h * W_IMG + wc;

    for (int t = 0; t < PT; t++) {
        __syncthreads();   /* protect wsm reuse across groups */
        /* load weight group t (27 output channels): wsm[tap][j] */
        for (int i = tid; i < 243 * CHG; i += 256) {
            int tap = i % 243;
            int j   = i / 243;
            wsm[tap * WPAD + j] = w_off[(size_t)(t * CHG + j) * 243 + tap];
        }
        if (tid < 243) wsm[tid * WPAD + 27] = 0.f;  /* pad col */
        __syncthreads();

        if (valid) {
            unsigned long long acc[14];
#pragma unroll
            for (int j = 0; j < 14; j++) {
                float bl = b_off[t * CHG + 2 * j];
                float bh = (2 * j + 1 < CHG) ? b_off[t * CHG + 2 * j + 1] : 0.f;
                acc[j] = pack2f(bl, bh);
            }
            for (int ic = 0; ic < CHG; ic++) {
#pragma unroll
                for (int ky = 0; ky < 3; ky++) {
#pragma unroll
                    for (int kx = 0; kx < 3; kx++) {
                        float gv = gs[(ic * 4 + ty + ky) * GSW + tx + kx];
                        unsigned long long g2 = pack2f(gv, gv);
                        const ulonglong2* wr =
                            (const ulonglong2*)(wsm + (ic * 9 + ky * 3 + kx) * WPAD);
#pragma unroll
                        for (int q = 0; q < 7; q++) {
                            ulonglong2 p = wr[q];
                            acc[2 * q]     = ffma2(g2, p.x, acc[2 * q]);
                            acc[2 * q + 1] = ffma2(g2, p.y, acc[2 * q + 1]);
                        }
                    }
                }
            }
            float r[28];
#pragma unroll
            for (int j = 0; j < 14; j++) unpack2f(acc[j], r[2 * j], r[2 * j + 1]);

            /* channels 0..17: offsets, fp16-rounded */
            float* ob = out_off + (size_t)(b * PT + t) * 18 * HW + pix;
#pragma unroll
            for (int j = 0; j < 18; j++)
                ob[(size_t)j * HW] = __half2float(__float2half(r[j]));

            /* channels 18..26: softmax + fp16 round */
            float m = r[18];
#pragma unroll
            for (int j = 19; j < 27; j++) m = fmaxf(m, r[j]);
            float e[9], s = 0.f;
#pragma unroll
            for (int j = 0; j < 9; j++) { e[j] = expf(r[18 + j] - m); s += e[j]; }
            float* ab = out_aff + (size_t)(b * PT + t) * 9 * HW + pix;
#pragma unroll
            for (int j = 0; j < 9; j++)
                ab[(size_t)j * HW] = __half2float(__float2half(e[j] / s));
        }
    }
}

/* ---------------- deformable propagation step ---------------- */
__device__ __forceinline__ float samp(const float* __restrict__ fb, int y, int x) {
    if ((unsigned)y < H_IMG && (unsigned)x < W_IMG) return fb[y * W_IMG + x];
    return 0.f;
}

__global__ void __launch_bounds__(256)
prop_kernel(const float* __restrict__ feat_in,
            const float* __restrict__ off,
            const float* __restrict__ aff,
            const float* __restrict__ confid,
            const float* __restrict__ ffix,
            const float* __restrict__ wf,
            const float* __restrict__ bf,
            float* __restrict__ fout,
            float* __restrict__ fout2,
            int t)
{
    int p = blockIdx.x * 256 + threadIdx.x;
    if (p >= NB * HW) return;
    int b   = p / HW;
    int rem = p - b * HW;
    int h   = rem / W_IMG;
    int w   = rem - h * W_IMG;

    const float* fb = feat_in + (size_t)b * HW;
    const float* ob = off + (size_t)(b * PT + t) * 18 * HW + rem;
    const float* ab = aff + (size_t)(b * PT + t) * 9 * HW + rem;

    float sum = 0.f;
#pragma unroll
    for (int k = 0; k < 9; k++) {
        float dy = ob[(size_t)(2 * k) * HW];
        float dx = ob[(size_t)(2 * k + 1) * HW];
        float a  = ab[(size_t)k * HW];
        float ys = (float)h + (float)(k / 3 - 1) + dy;
        float xs = (float)w + (float)(k % 3 - 1) + dx;
        float y0 = floorf(ys), x0 = floorf(xs);
        float wy = ys - y0,  wx = xs - x0;
        int y0i = (int)y0, x0i = (int)x0;
        float v00 = samp(fb, y0i,     x0i);
        float v01 = samp(fb, y0i,     x0i + 1);
        float v10 = samp(fb, y0i + 1, x0i);
        float v11 = samp(fb, y0i + 1, x0i + 1);
        float v = v00 * (1.f - wy) * (1.f - wx)
                + v01 * (1.f - wy) * wx
                + v10 * wy * (1.f - wx)
                + v11 * wy * wx;
        sum += v * a * wf[k];
    }
    float prop = sum + bf[0];
    float fx   = ffix[p];
    float sg   = (fx > 0.f) ? 1.f : ((fx < 0.f) ? -1.f : 0.f);
    float conf = sg * (1.f / (1.f + expf(-confid[p])));
    float o    = (1.f - conf) * prop + conf * fx;
    fout[p] = o;
    if (fout2) fout2[p] = o;
}

/* ------------------------- launch ------------------------- */
extern "C" void kernel_launch(void* const* d_in, const int* in_sizes, int n_in,
                              void* d_out, int out_size)
{
    const float* feat_init  = (const float*)d_in[0];
    const float* guidance   = (const float*)d_in[1];
    const float* confidence = (const float*)d_in[2];
    const float* feat_fix   = (const float*)d_in[3];
    const float* w_off      = (const float*)d_in[4];
    const float* b_off      = (const float*)d_in[5];
    const float* w_f        = (const float*)d_in[6];
    const float* b_f        = (const float*)d_in[7];

    float* out = (float*)d_out;
    const size_t NPIX = (size_t)NB * HW;

    /* flattened tuple layout: feat | list_feat(3) | offsets | affs */
    float* out_feat = out;
    float* out_list = out + NPIX;
    float* out_off  = out + 4 * NPIX;
    float* out_aff  = out_off + (size_t)NB * PT * 18 * HW;

    cudaFuncSetAttribute(conv_off_aff_kernel,
                         cudaFuncAttributeMaxDynamicSharedMemorySize, SMEM_BYTES);

    dim3 cg((W_IMG + TW - 1) / TW, H_IMG / TH, NB);
    conv_off_aff_kernel<<<cg, 256, SMEM_BYTES>>>(guidance, w_off, b_off,
                                                 out_off, out_aff);

    int np = NB * HW;
    int blocks = (np + 255) / 256;
    prop_kernel<<<blocks, 256>>>(feat_init, out_off, out_aff, confidence,
                                 feat_fix, w_f, b_f, out_list, nullptr, 0);
    prop_kernel<<<blocks, 256>>>(out_list, out_off, out_aff, confidence,
                                 feat_fix, w_f, b_f, out_list + NPIX, nullptr, 1);
    prop_kernel<<<blocks, 256>>>(out_list + NPIX, out_off, out_aff, confidence,
                                 feat_fix, w_f, b_f, out_list + 2 * NPIX,
                                 out_feat, 2);
}

// round 2
// speedup vs baseline: 2.3416x; 2.3416x over previous
#include <cuda_runtime.h>
#include <cuda_fp16.h>

#define W_IMG 1216
#define H_IMG 352
#define NB    4
#define HW    (H_IMG * W_IMG)     /* 428032 */
#define CHG   27
#define PT    3
#define GSW   136                 /* patch row stride (floats), 130 used */
#define SMEM_BYTES (CHG * 4 * GSW * 4)

/* reordered weights: [t][tap][32]  (half h at float offset 16*h, 14 used + 2 pad) */
__device__ float g_wre[PT * 243 * 32];
__device__ float g_sink;

/* ---------- packed f32x2 helpers (Blackwell FFMA2) ---------- */
__device__ __forceinline__ unsigned long long pack2f(float a, float b) {
    unsigned long long r;
    asm("mov.b64 %0, {%1, %2};" : "=l"(r)
        : "r"(__float_as_uint(a)), "r"(__float_as_uint(b)));
    return r;
}
__device__ __forceinline__ unsigned long long ffma2(unsigned long long a,
                                                    unsigned long long b,
                                                    unsigned long long c) {
    unsigned long long d;
    asm("fma.rn.f32x2 %0, %1, %2, %3;" : "=l"(d) : "l"(a), "l"(b), "l"(c));
    return d;
}
__device__ __forceinline__ void unpack2f(unsigned long long v, float& lo, float& hi) {
    unsigned int a, b;
    asm("mov.b64 {%0, %1}, %2;" : "=r"(a), "=r"(b) : "l"(v));
    lo = __uint_as_float(a);
    hi = __uint_as_float(b);
}
__device__ __forceinline__ float h2(float x) {
    return __half2float(__float2half(x));
}

/* -------------------- weight reorder -------------------- */
__global__ void reorder_kernel(const float* __restrict__ w_off) {
    int i = blockIdx.x * 256 + threadIdx.x;
    if (i >= PT * 243 * 32) return;
    int j   = i & 31;
    int tap = (i >> 5) % 243;
    int t   = i / (243 * 32);
    int hf  = j >> 4;
    int jj  = j & 15;
    int co  = hf * 14 + jj;
    float v = 0.f;
    if (jj < 14 && co < CHG)
        v = w_off[(size_t)(t * CHG + co) * 243 + tap];
    g_wre[i] = v;
}

__global__ void dummy_kernel() { if (threadIdx.x == 0) g_sink = 0.f; }

/* ---------------------------------------------------------------
 * Conv 3x3 (27 -> 81), SAME zero pad, fused fp16-round + softmax.
 * 128 threads: tx(32) x ty(2 rows) x hf(2 oc-halves).
 * Each thread: 4 pixels x 14 output channels (28 u64 f32x2 accums).
 * Weights via __ldg (L1 broadcast dedup), guidance via LDS.128.
 * --------------------------------------------------------------- */
__global__ void __launch_bounds__(128, 3)
conv_kernel(const float* __restrict__ g,
            const float* __restrict__ b_off,
            float* __restrict__ out_off,
            float* __restrict__ out_aff)
{
    extern __shared__ float gs[];           /* CHG * 4 * GSW */
    const int tid = threadIdx.x;
    const int tx  = tid & 31;
    const int ty  = (tid >> 5) & 1;
    const int hf  = tid >> 6;
    const int x0  = blockIdx.x * 128;
    const int h0  = blockIdx.y * 2;
    const int b   = blockIdx.z;

    /* cooperative patch load: rows h0-1..h0+2, cols x0-1..x0+128, zero pad */
    for (int i = tid; i < CHG * 4 * GSW; i += 128) {
        int c  = i % GSW;
        int rr = i / GSW;
        int r  = rr & 3;
        int ic = rr >> 2;
        int gh = h0 - 1 + r;
        int gw = x0 - 1 + c;
        float v = 0.f;
        if (c < 130 && (unsigned)gh < H_IMG && (unsigned)gw < W_IMG)
            v = g[(size_t)(b * CHG + ic) * HW + gh * W_IMG + gw];
        gs[i] = v;
    }
    __syncthreads();

    const int xp = x0 + tx * 4;             /* first of this thread's 4 pixels */
    if (xp >= W_IMG) return;                /* W%4==0 -> all-or-none per thread */
    const int hh  = h0 + ty;
    const int pix = hh * W_IMG + xp;

    for (int t = 0; t < PT; t++) {
        /* bias init (packed pairs) */
        unsigned long long acc[28];
        float bv[14];
#pragma unroll
        for (int j = 0; j < 14; j++) {
            int co = hf * 14 + j;
            bv[j] = (co < CHG) ? __ldg(b_off + t * CHG + co) : 0.f;
        }
#pragma unroll
        for (int p = 0; p < 4; p++)
#pragma unroll
            for (int q = 0; q < 7; q++)
                acc[p * 7 + q] = pack2f(bv[2 * q], bv[2 * q + 1]);

        const float* wbase = g_wre + (size_t)t * 243 * 32 + hf * 16;

        for (int ic = 0; ic < CHG; ic++) {
            /* 3 rows x 8-col window -> packed g2, reused for all 9 taps */
            unsigned long long g2[3][6];
#pragma unroll
            for (int ky = 0; ky < 3; ky++) {
                const float4* rp =
                    (const float4*)(gs + (ic * 4 + ty + ky) * GSW + tx * 4);
                float4 a0 = rp[0];
                float4 a1 = rp[1];
                float f[8] = {a0.x, a0.y, a0.z, a0.w, a1.x, a1.y, a1.z, a1.w};
#pragma unroll
                for (int c = 0; c < 6; c++) g2[ky][c] = pack2f(f[c], f[c]);
            }
#pragma unroll
            for (int ky = 0; ky < 3; ky++) {
#pragma unroll
                for (int kx = 0; kx < 3; kx++) {
                    const float* wr = wbase + (ic * 9 + ky * 3 + kx) * 32;
                    const ulonglong2* wp = (const ulonglong2*)wr;
                    ulonglong2 u0 = __ldg(wp);
                    ulonglong2 u1 = __ldg(wp + 1);
                    ulonglong2 u2 = __ldg(wp + 2);
                    unsigned long long w6 =
                        __ldg((const unsigned long long*)wr + 6);
                    unsigned long long w[7] = {u0.x, u0.y, u1.x, u1.y,
                                               u2.x, u2.y, w6};
#pragma unroll
                    for (int p = 0; p < 4; p++) {
                        unsigned long long gv = g2[ky][p + kx];
#pragma unroll
                        for (int q = 0; q < 7; q++)
                            acc[p * 7 + q] = ffma2(gv, w[q], acc[p * 7 + q]);
                    }
                }
            }
        }

        /* epilogue */
        float r[4][14];
#pragma unroll
        for (int p = 0; p < 4; p++)
#pragma unroll
            for (int q = 0; q < 7; q++)
                unpack2f(acc[p * 7 + q], r[p][2 * q], r[p][2 * q + 1]);

        float* ob = out_off + (size_t)(b * PT + t) * 18 * HW;
        if (hf == 0) {
            /* channels 0..13: offsets */
#pragma unroll
            for (int j = 0; j < 14; j++) {
                float4 v = make_float4(h2(r[0][j]), h2(r[1][j]),
                                       h2(r[2][j]), h2(r[3][j]));
                *(float4*)(ob + (size_t)j * HW + pix) = v;
            }
        } else {
            /* channels 14..17: offsets */
#pragma unroll
            for (int j = 0; j < 4; j++) {
                float4 v = make_float4(h2(r[0][j]), h2(r[1][j]),
                                       h2(r[2][j]), h2(r[3][j]));
                *(float4*)(ob + (size_t)(14 + j) * HW + pix) = v;
            }
            /* channels 18..26 (r[p][4..12]): softmax + fp16 round */
            float* ab = out_aff + (size_t)(b * PT + t) * 9 * HW;
            float e[4][9];
#pragma unroll
            for (int p = 0; p < 4; p++) {
                float m = r[p][4];
#pragma unroll
                for (int j = 5; j < 13; j++) m = fmaxf(m, r[p][j]);
                float s = 0.f;
#pragma unroll
                for (int j = 0; j < 9; j++) {
                    e[p][j] = expf(r[p][4 + j] - m);
                    s += e[p][j];
                }
                float inv = 1.f / s;
#pragma unroll
                for (int j = 0; j < 9; j++) e[p][j] = h2(e[p][j] * inv);
            }
#pragma unroll
            for (int j = 0; j < 9; j++) {
                float4 v = make_float4(e[0][j], e[1][j], e[2][j], e[3][j]);
                *(float4*)(ab + (size_t)j * HW + pix) = v;
            }
        }
    }
}

/* ---------------- deformable propagation step ---------------- */
__device__ __forceinline__ float samp(const float* __restrict__ fb, int y, int x) {
    if ((unsigned)y < H_IMG && (unsigned)x < W_IMG) return fb[y * W_IMG + x];
    return 0.f;
}

__global__ void __launch_bounds__(256)
prop_kernel(const float* __restrict__ feat_in,
            const float* __restrict__ off,
            const float* __restrict__ aff,
            const float* __restrict__ confid,
            const float* __restrict__ ffix,
            const float* __restrict__ wf,
            const float* __restrict__ bf,
            float* __restrict__ fout,
            float* __restrict__ fout2,
            int t)
{
    int p = blockIdx.x * 256 + threadIdx.x;
    if (p >= NB * HW) return;
    int b   = p / HW;
    int rem = p - b * HW;
    int h   = rem / W_IMG;
    int w   = rem - h * W_IMG;

    const float* fb = feat_in + (size_t)b * HW;
    const float* ob = off + (size_t)(b * PT + t) * 18 * HW + rem;
    const float* ab = aff + (size_t)(b * PT + t) * 9 * HW + rem;

    float sum = 0.f;
#pragma unroll
    for (int k = 0; k < 9; k++) {
        float dy = ob[(size_t)(2 * k) * HW];
        float dx = ob[(size_t)(2 * k + 1) * HW];
        float a  = ab[(size_t)k * HW];
        float ys = (float)h + (float)(k / 3 - 1) + dy;
        float xs = (float)w + (float)(k % 3 - 1) + dx;
        float y0 = floorf(ys), x0 = floorf(xs);
        float wy = ys - y0,  wx = xs - x0;
        int y0i = (int)y0, x0i = (int)x0;
        float v00 = samp(fb, y0i,     x0i);
        float v01 = samp(fb, y0i,     x0i + 1);
        float v10 = samp(fb, y0i + 1, x0i);
        float v11 = samp(fb, y0i + 1, x0i + 1);
        float v = v00 * (1.f - wy) * (1.f - wx)
                + v01 * (1.f - wy) * wx
                + v10 * wy * (1.f - wx)
                + v11 * wy * wx;
        sum += v * a * wf[k];
    }
    float prop = sum + bf[0];
    float fx   = ffix[p];
    float sg   = (fx > 0.f) ? 1.f : ((fx < 0.f) ? -1.f : 0.f);
    float conf = sg * (1.f / (1.f + expf(-confid[p])));
    float o    = (1.f - conf) * prop + conf * fx;
    fout[p] = o;
    if (fout2) fout2[p] = o;
}

/* ------------------------- launch ------------------------- */
extern "C" void kernel_launch(void* const* d_in, const int* in_sizes, int n_in,
                              void* d_out, int out_size)
{
    const float* feat_init  = (const float*)d_in[0];
    const float* guidance   = (const float*)d_in[1];
    const float* confidence = (const float*)d_in[2];
    const float* feat_fix   = (const float*)d_in[3];
    const float* w_off      = (const float*)d_in[4];
    const float* b_off      = (const float*)d_in[5];
    const float* w_f        = (const float*)d_in[6];
    const float* b_f        = (const float*)d_in[7];

    float* out = (float*)d_out;
    const size_t NPIX = (size_t)NB * HW;

    /* flattened tuple: feat | list_feat(3) | offsets | affs */
    float* out_feat = out;
    float* out_list = out + NPIX;
    float* out_off  = out + 4 * NPIX;
    float* out_aff  = out_off + (size_t)NB * PT * 18 * HW;

    cudaFuncSetAttribute(conv_kernel,
                         cudaFuncAttributeMaxDynamicSharedMemorySize, SMEM_BYTES);

    /* launches 1-5: reorder + 4 dummies -> ncu (-s 5) captures conv at #6 */
    reorder_kernel<<<(PT * 243 * 32 + 255) / 256, 256>>>(w_off);
    dummy_kernel<<<1, 32>>>();
    dummy_kernel<<<1, 32>>>();
    dummy_kernel<<<1, 32>>>();
    dummy_kernel<<<1, 32>>>();

    dim3 cg((W_IMG + 127) / 128, H_IMG / 2, NB);
    conv_kernel<<<cg, 128, SMEM_BYTES>>>(guidance, b_off, out_off, out_aff);

    int np = NB * HW;
    int blocks = (np + 255) / 256;
    prop_kernel<<<blocks, 256>>>(feat_init, out_off, out_aff, confidence,
                                 feat_fix, w_f, b_f, out_list, nullptr, 0);
    prop_kernel<<<blocks, 256>>>(out_list, out_off, out_aff, confidence,
                                 feat_fix, w_f, b_f, out_list + NPIX, nullptr, 1);
    prop_kernel<<<blocks, 256>>>(out_list + NPIX, out_off, out_aff, confidence,
                                 feat_fix, w_f, b_f, out_list + 2 * NPIX,
                                 out_feat, 2);
}